// round 8
// baseline (speedup 1.0000x reference)
#include <cuda_runtime.h>
#include <cstdint>

#define NQ   4
#define DIM  16
#define NC   4
#define BLK  512
#define WARPS_PER_BLK 16
#define GRID 148
#define WARPS_TOTAL (GRID * WARPS_PER_BLK)      // 2368
#define GROUP_ROWS 32
#define SLOT_PITCH 52                           // words/sample: 52 mod 32 spacing -> conflict-free LDS.128
#define WARP_SLOTS (GROUP_ROWS * SLOT_PITCH)    // 1664 words = 6656 B
#define SMEM_BYTES (WARPS_PER_BLK * WARP_SLOTS * 4)  // 106496
#define MAX_G 4                                 // ceil(8192 / 2368)

__device__ double g_acc[8];
__device__ float  g_scale[NC];
__device__ float  g_shift[NC];
__device__ unsigned g_cnt;
__device__ int g_flag;

__global__ void k_init() {
    if (threadIdx.x < 8) g_acc[threadIdx.x] = 0.0;
    if (threadIdx.x == 0) { g_cnt = 0u; g_flag = 0; }
}

__global__ void __launch_bounds__(BLK, 1) k_persist(
    const float* __restrict__ x,
    const float* __restrict__ wts,
    const float* __restrict__ W,
    const float* __restrict__ bias,
    const float* __restrict__ gamma,
    const float* __restrict__ beta,
    float* __restrict__ out,
    int B, float invB)
{
    extern __shared__ float sw[];
    const int t = threadIdx.x;
    const int lane = t & 31;
    const int wid  = t >> 5;
    const int gw   = blockIdx.x * WARPS_PER_BLK + wid;
    float* wslots = sw + wid * WARP_SLOTS;

    const int totalGroups = B / GROUP_ROWS;     // 8192

    float wc[8], ws[8];
    #pragma unroll
    for (int i = 0; i < 8; i++) __sincosf(wts[i] * 0.5f, &ws[i], &wc[i]);

    float lg[MAX_G][4];
    float sum0=0.f,sum1=0.f,sum2=0.f,sum3=0.f, sq0=0.f,sq1=0.f,sq2=0.f,sq3=0.f;

    #pragma unroll 1
    for (int kg = 0; kg < MAX_G; kg++) {
        int g = gw + kg * WARPS_TOTAL;
        if (g >= totalGroups) break;

        // ---- (a) streaming load + register partial-reduce + tiny STS ----
        // group = 32 samples x 144 floats, contiguous = 1152 float4.
        // lane reads float4 p = lane + 32*kk (fully coalesced, nL=4).
        const float4* gsrc = (const float4*)(x + (size_t)g * GROUP_ROWS * 144);
        #pragma unroll
        for (int j = 0; j < 4; j++) {
            #pragma unroll
            for (int k9 = 0; k9 < 9; k9++) {
                unsigned p = (unsigned)lane + 32u * (unsigned)(j * 9 + k9);
                float4 v = __ldcs(gsrc + p);
                unsigned s = p / 36u;          // sample in group
                unsigned q = p % 36u;          // float4 within sample
                unsigned r = q / 3u;           // image row 0..11
                unsigned pos = q % 3u;         // position within row
                float a = v.x + v.y;
                float b = v.z + v.w;
                float* base = wslots + s * SLOT_PITCH + r * 4u;
                // row slots: [0]=left4(cols0-3) [1]=left2(4,5) [2]=right2(6,7) [3]=right4(8-11)
                if (pos == 0)      { base[0] = a + b; }
                else if (pos == 1) { base[1] = a; base[2] = b; }
                else               { base[3] = a + b; }
            }
        }
        __syncwarp();

        // ---- (b) per-lane quadrant sums: 12 conflict-free LDS.128 ----
        float s0 = 0.f, s1 = 0.f, s2 = 0.f, s3 = 0.f;   // TL TR BL BR
        {
            const float* mine = wslots + lane * SLOT_PITCH;
            #pragma unroll
            for (int r = 0; r < 12; r++) {
                float4 v = *(const float4*)(mine + r * 4);
                float L = v.x + v.y;
                float R = v.z + v.w;
                if (r < 6) { s0 += L; s1 += R; }
                else       { s2 += L; s3 += R; }
            }
        }
        __syncwarp();   // all lanes done reading before next iteration's STS

        // ---- circuit ----
        const float inv72 = 1.f / 72.f;   // (1/36) * 0.5
        float pc4[4], ps4[4];
        __sincosf(s0 * inv72, &ps4[0], &pc4[0]);
        __sincosf(s1 * inv72, &ps4[1], &pc4[1]);
        __sincosf(s2 * inv72, &ps4[2], &pc4[2]);
        __sincosf(s3 * inv72, &ps4[3], &pc4[3]);

        float re[DIM], im[DIM];
        #pragma unroll
        for (int k = 0; k < DIM; k++) {
            float m = ((k & 8) ? ps4[0] : pc4[0])
                    * ((k & 4) ? ps4[1] : pc4[1])
                    * ((k & 2) ? ps4[2] : pc4[2])
                    * ((k & 1) ? ps4[3] : pc4[3]);
            int pc = __popc(k) & 3;
            re[k] = (pc == 0) ? m : ((pc == 2) ? -m : 0.f);
            im[k] = (pc == 1) ? -m : ((pc == 3) ? m : 0.f);
        }
        int idx = 0;
        #pragma unroll
        for (int d = 0; d < 2; d++) {
            #pragma unroll
            for (int w = 0; w < NQ; w++) {
                float cc = wc[idx], ss = ws[idx]; idx++;
                int bit = 1 << (3 - w);
                #pragma unroll
                for (int k = 0; k < DIM; k++) {
                    if (!(k & bit)) {
                        int k1 = k | bit;
                        float r0 = re[k], r1 = re[k1];
                        re[k]  = cc * r0 - ss * r1;
                        re[k1] = ss * r0 + cc * r1;
                        float i0 = im[k], i1 = im[k1];
                        im[k]  = cc * i0 - ss * i1;
                        im[k1] = ss * i0 + cc * i1;
                    }
                }
            }
            #pragma unroll
            for (int k = 0; k < DIM; k++) {
                int par = (((k >> 3) & (k >> 2)) ^ ((k >> 2) & (k >> 1)) ^ ((k >> 1) & k)) & 1;
                if (par) { re[k] = -re[k]; im[k] = -im[k]; }
            }
        }
        float q0=0.f, q1=0.f, q2=0.f, q3=0.f;
        #pragma unroll
        for (int k = 0; k < DIM; k++) {
            float p = re[k] * re[k] + im[k] * im[k];
            q0 += (k & 8) ? -p : p;
            q1 += (k & 4) ? -p : p;
            q2 += (k & 2) ? -p : p;
            q3 += (k & 1) ? -p : p;
        }
        #pragma unroll
        for (int c2 = 0; c2 < NC; c2++) {
            lg[kg][c2] = __ldg(&bias[c2])
                       + q0 * __ldg(&W[c2*4+0]) + q1 * __ldg(&W[c2*4+1])
                       + q2 * __ldg(&W[c2*4+2]) + q3 * __ldg(&W[c2*4+3]);
        }
        sum0 += lg[kg][0]; sum1 += lg[kg][1]; sum2 += lg[kg][2]; sum3 += lg[kg][3];
        sq0 += lg[kg][0]*lg[kg][0]; sq1 += lg[kg][1]*lg[kg][1];
        sq2 += lg[kg][2]*lg[kg][2]; sq3 += lg[kg][3]*lg[kg][3];
    }

    // ---- block reduction ----
    float red[8] = {sum0,sum1,sum2,sum3,sq0,sq1,sq2,sq3};
    #pragma unroll
    for (int off = 16; off > 0; off >>= 1) {
        #pragma unroll
        for (int j = 0; j < 8; j++)
            red[j] += __shfl_down_sync(0xFFFFFFFFu, red[j], off);
    }
    __syncthreads();
    float* rsm = sw;        // reuse smem
    if (lane == 0) {
        #pragma unroll
        for (int j = 0; j < 8; j++) rsm[j * WARPS_PER_BLK + wid] = red[j];
    }
    __syncthreads();
    if (t < 8) {
        float acc = 0.f;
        #pragma unroll
        for (int wgi = 0; wgi < WARPS_PER_BLK; wgi++) acc += rsm[t * WARPS_PER_BLK + wgi];
        atomicAdd(&g_acc[t], (double)acc);
        __threadfence();
    }
    __syncthreads();

    // ---- grid barrier (148 blocks, 1/SM, all co-resident) ----
    if (t == 0) {
        unsigned r = atomicAdd(&g_cnt, 1u);
        if (r == gridDim.x - 1u) {
            #pragma unroll
            for (int c2 = 0; c2 < NC; c2++) {
                double m = g_acc[c2] * (double)invB;
                double v = g_acc[4 + c2] * (double)invB - m * m;
                float inv = rsqrtf((float)v + 1e-5f);
                g_scale[c2] = gamma[c2] * inv;
                g_shift[c2] = beta[c2] - (float)m * inv * gamma[c2];
            }
            __threadfence();
            atomicExch(&g_flag, 1);
        } else {
            while (atomicAdd(&g_flag, 0) == 0) __nanosleep(64);
        }
    }
    __syncthreads();

    float sc[4], sh[4];
    #pragma unroll
    for (int c2 = 0; c2 < NC; c2++) {
        sc[c2] = *((volatile float*)&g_scale[c2]);
        sh[c2] = *((volatile float*)&g_shift[c2]);
    }

    // ---- coalesced normalized write ----
    float4* o4 = (float4*)out;
    #pragma unroll
    for (int kg = 0; kg < MAX_G; kg++) {
        int g = gw + kg * WARPS_TOTAL;
        if (g < totalGroups) {
            o4[(size_t)g * GROUP_ROWS + lane] =
                make_float4(lg[kg][0]*sc[0]+sh[0], lg[kg][1]*sc[1]+sh[1],
                            lg[kg][2]*sc[2]+sh[2], lg[kg][3]*sc[3]+sh[3]);
        }
    }
}

extern "C" void kernel_launch(void* const* d_in, const int* in_sizes, int n_in,
                              void* d_out, int out_size) {
    const float* x     = (const float*)d_in[0];
    const float* wts   = (const float*)d_in[1];
    const float* W     = (const float*)d_in[2];
    const float* bias  = (const float*)d_in[3];
    const float* gamma = (const float*)d_in[4];
    const float* beta  = (const float*)d_in[5];
    float* out = (float*)d_out;

    int B = in_sizes[0] / 144;    // 262144

    cudaFuncSetAttribute(k_persist, cudaFuncAttributeMaxDynamicSharedMemorySize, SMEM_BYTES);

    k_init<<<1, 32>>>();
    k_persist<<<GRID, BLK, SMEM_BYTES>>>(x, wts, W, bias, gamma, beta, out,
                                         B, 1.0f / (float)B);
}

// round 9
// speedup vs baseline: 2.2590x; 2.2590x over previous
#include <cuda_runtime.h>
#include <cstdint>

#define NQ   4
#define DIM  16
#define NC   4
#define BLK  256
#define GRID 296                       // exactly 2 blocks per SM, all co-resident
#define CHUNK_ROWS 64
#define ROW_PITCH 592                  // bytes/sample-row in smem; conflict-free LDS.128
#define CHUNK_BYTES (CHUNK_ROWS * ROW_PITCH)   // 37888
#define PART_PITCH 9                   // words per sample in partial array (conflict-free)
#define MAX_IT 4                       // ceil(1024 units / 296 blocks)

// smem layout (bytes)
#define OFF_BUF0  0
#define OFF_BUF1  CHUNK_BYTES                          // 37888
#define OFF_PART  (2 * CHUNK_BYTES)                    // 75776  (256*9 floats = 9216B)
#define OFF_LSM   (OFF_PART + 256 * PART_PITCH * 4)    // 84992  (4*256*4 floats = 16384B)
#define OFF_CONST (OFF_LSM + MAX_IT * 256 * 4 * 4)     // 101376 (40 floats)
#define SMEM_BYTES (OFF_CONST + 40 * 4)                // 101536

__device__ double g_acc[8];
__device__ float  g_scale[NC];
__device__ float  g_shift[NC];
__device__ unsigned g_cnt;
__device__ int g_flag;

__global__ void k_init() {
    if (threadIdx.x < 8) g_acc[threadIdx.x] = 0.0;
    if (threadIdx.x == 0) { g_cnt = 0u; g_flag = 0; }
}

__device__ __forceinline__ void cp16(char* dst_smem, const float4* src) {
    unsigned d = (unsigned)__cvta_generic_to_shared(dst_smem);
    asm volatile("cp.async.cg.shared.global [%0], [%1], 16;\n" :: "r"(d), "l"(src));
}
__device__ __forceinline__ void cp_commit() { asm volatile("cp.async.commit_group;\n"); }
template<int N> __device__ __forceinline__ void cp_wait() {
    asm volatile("cp.async.wait_group %0;\n" :: "n"(N));
}

__global__ void __launch_bounds__(BLK, 2) k_persist(
    const float* __restrict__ x,
    const float* __restrict__ wts,
    const float* __restrict__ W,
    const float* __restrict__ bias,
    const float* __restrict__ gamma,
    const float* __restrict__ beta,
    float* __restrict__ out,
    int units, float invB)            // units = B/256
{
    extern __shared__ char smem[];
    char*  buf0 = smem + OFF_BUF0;
    char*  buf1 = smem + OFF_BUF1;
    float* part = (float*)(smem + OFF_PART);
    float* lsm  = (float*)(smem + OFF_LSM);
    float* csm  = (float*)(smem + OFF_CONST);  // [0:8)=wc [8:16)=ws [16:32)=W [32:36)=bias

    const int t = threadIdx.x;
    const int b = blockIdx.x;

    // ---- init constants in smem ----
    if (t < 8) {
        float c, s; __sincosf(wts[t] * 0.5f, &s, &c);
        csm[t] = c; csm[8 + t] = s;
    } else if (t < 24) {
        csm[16 + (t - 8)] = W[t - 8];
    } else if (t < 28) {
        csm[32 + (t - 24)] = bias[t - 24];
    }

    // precompute per-thread cp.async smem offsets (9 float4 per 64-row chunk)
    unsigned coff[9];
    #pragma unroll
    for (int k = 0; k < 9; k++) {
        int idx = t + BLK * k;
        int row = idx / 36, col = idx % 36;
        coff[k] = (unsigned)row * ROW_PITCH + (unsigned)col * 16u;
    }
    __syncthreads();

    // issue one 64-row chunk (coalesced 2304 float4)
    auto issue64 = [&](char* dst, size_t row0) {
        const float4* src = (const float4*)(x + row0 * 144);
        #pragma unroll
        for (int k = 0; k < 9; k++) cp16(dst + coff[k], src + (t + BLK * k));
        cp_commit();
    };
    // pool one chunk: thread -> (sample row t&63, quarter t>>6); write (L,R) partials
    auto pool64 = [&](const char* buf, int c) {
        int r = t & 63, q = t >> 6;
        const char* rb = buf + (unsigned)r * ROW_PITCH + (unsigned)q * 144u;
        float L = 0.f, R = 0.f;
        #pragma unroll
        for (int j = 0; j < 9; j++) {
            float4 v = *(const float4*)(rb + 16 * j);
            int pos = j % 3;
            if (pos == 0)      { L += v.x + v.y + v.z + v.w; }
            else if (pos == 1) { L += v.x + v.y; R += v.z + v.w; }
            else               { R += v.x + v.y + v.z + v.w; }
        }
        float* p = part + (unsigned)(c * 64 + r) * PART_PITCH + 2u * q;
        p[0] = L; p[1] = R;
    };

    float sum0=0.f,sum1=0.f,sum2=0.f,sum3=0.f, sq0=0.f,sq1=0.f,sq2=0.f,sq3=0.f;

    // prologue: chunks 0,1 of first unit
    {
        size_t r0 = (size_t)b * 256;
        issue64(buf0, r0);
        issue64(buf1, r0 + CHUNK_ROWS);
    }

    #pragma unroll 1
    for (int it = 0; it < MAX_IT; it++) {
        int u = b + it * GRID;
        if (u >= units) break;
        size_t rb0 = (size_t)u * 256;
        bool nv = (u + GRID) < units;
        size_t nb0 = (size_t)(u + GRID) * 256;

        // c0
        cp_wait<1>(); __syncthreads();
        pool64(buf0, 0); __syncthreads();
        issue64(buf0, rb0 + 2 * CHUNK_ROWS);
        // c1
        cp_wait<1>(); __syncthreads();
        pool64(buf1, 1); __syncthreads();
        issue64(buf1, rb0 + 3 * CHUNK_ROWS);
        // c2
        cp_wait<1>(); __syncthreads();
        pool64(buf0, 2); __syncthreads();
        if (nv) issue64(buf0, nb0);
        // c3
        if (nv) { cp_wait<1>(); } else { cp_wait<0>(); }
        __syncthreads();
        pool64(buf1, 3); __syncthreads();
        if (nv) issue64(buf1, nb0 + CHUNK_ROWS);

        // ---- per-thread sample: read 8 partials, run circuit ----
        const float* pp = part + (unsigned)t * PART_PITCH;
        float TL = pp[0] + pp[2], TR = pp[1] + pp[3];
        float BL = pp[4] + pp[6], BR = pp[5] + pp[7];

        const float inv72 = 1.f / 72.f;   // (1/36)*0.5 half-angle
        float cp4[4], sp4[4];
        __sincosf(TL * inv72, &sp4[0], &cp4[0]);
        __sincosf(TR * inv72, &sp4[1], &cp4[1]);
        __sincosf(BL * inv72, &sp4[2], &cp4[2]);
        __sincosf(BR * inv72, &sp4[3], &cp4[3]);

        // per-wire vector after RX(p) then RY(w_layer1): v = RY * (cos p, -i sin p)
        float v0r[4], v0i[4], v1r[4], v1i[4];
        #pragma unroll
        for (int i = 0; i < 4; i++) {
            float cw = csm[i], sw = csm[8 + i];
            v0r[i] =  cw * cp4[i];  v0i[i] =  sw * sp4[i];
            v1r[i] =  sw * cp4[i];  v1i[i] = -cw * sp4[i];
        }
        // pair tensor products: wires (0,1) and (2,3)
        float p01r[4], p01i[4], p23r[4], p23i[4];
        #pragma unroll
        for (int a = 0; a < 2; a++) {
            float ar0 = a ? v1r[0] : v0r[0], ai0 = a ? v1i[0] : v0i[0];
            float ar2 = a ? v1r[2] : v0r[2], ai2 = a ? v1i[2] : v0i[2];
            #pragma unroll
            for (int c = 0; c < 2; c++) {
                float br1 = c ? v1r[1] : v0r[1], bi1 = c ? v1i[1] : v0i[1];
                float br3 = c ? v1r[3] : v0r[3], bi3 = c ? v1i[3] : v0i[3];
                p01r[a*2+c] = ar0 * br1 - ai0 * bi1;
                p01i[a*2+c] = ar0 * bi1 + ai0 * br1;
                p23r[a*2+c] = ar2 * br3 - ai2 * bi3;
                p23i[a*2+c] = ar2 * bi3 + ai2 * br3;
            }
        }
        // full amplitudes + mid CZ sign (final CZ dropped: probs unaffected)
        float re[DIM], im[DIM];
        #pragma unroll
        for (int k = 0; k < DIM; k++) {
            int a = (k >> 2) & 3, c = k & 3;
            float rr = p01r[a] * p23r[c] - p01i[a] * p23i[c];
            float ii = p01r[a] * p23i[c] + p01i[a] * p23r[c];
            int par = (((k >> 3) & (k >> 2)) ^ ((k >> 2) & (k >> 1)) ^ ((k >> 1) & k)) & 1;
            re[k] = par ? -rr : rr;
            im[k] = par ? -ii : ii;
        }
        // RY layer 2
        #pragma unroll
        for (int w = 0; w < NQ; w++) {
            float cc = csm[4 + w], ss = csm[12 + w];
            int bit = 1 << (3 - w);
            #pragma unroll
            for (int k = 0; k < DIM; k++) {
                if (!(k & bit)) {
                    int k1 = k | bit;
                    float r0 = re[k], r1 = re[k1];
                    re[k]  = cc * r0 - ss * r1;
                    re[k1] = ss * r0 + cc * r1;
                    float i0 = im[k], i1 = im[k1];
                    im[k]  = cc * i0 - ss * i1;
                    im[k1] = ss * i0 + cc * i1;
                }
            }
        }
        float q0=0.f, q1=0.f, q2=0.f, q3=0.f;
        #pragma unroll
        for (int k = 0; k < DIM; k++) {
            float p = re[k] * re[k] + im[k] * im[k];
            q0 += (k & 8) ? -p : p;
            q1 += (k & 4) ? -p : p;
            q2 += (k & 2) ? -p : p;
            q3 += (k & 1) ? -p : p;
        }
        float l0 = csm[32] + q0*csm[16+0] + q1*csm[16+1] + q2*csm[16+2]  + q3*csm[16+3];
        float l1 = csm[33] + q0*csm[16+4] + q1*csm[16+5] + q2*csm[16+6]  + q3*csm[16+7];
        float l2 = csm[34] + q0*csm[16+8] + q1*csm[16+9] + q2*csm[16+10] + q3*csm[16+11];
        float l3 = csm[35] + q0*csm[16+12]+ q1*csm[16+13]+ q2*csm[16+14] + q3*csm[16+15];

        *(float4*)(lsm + (unsigned)(it * 256 + t) * 4u) = make_float4(l0, l1, l2, l3);
        sum0 += l0; sum1 += l1; sum2 += l2; sum3 += l3;
        sq0 += l0*l0; sq1 += l1*l1; sq2 += l2*l2; sq3 += l3*l3;
    }

    // ---- block reduction ----
    float red[8] = {sum0,sum1,sum2,sum3,sq0,sq1,sq2,sq3};
    #pragma unroll
    for (int off = 16; off > 0; off >>= 1) {
        #pragma unroll
        for (int j = 0; j < 8; j++)
            red[j] += __shfl_down_sync(0xFFFFFFFFu, red[j], off);
    }
    __syncthreads();
    float* rsm = part;   // reuse partial area
    int lane = t & 31, wid = t >> 5;
    if (lane == 0) {
        #pragma unroll
        for (int j = 0; j < 8; j++) rsm[j * 8 + wid] = red[j];
    }
    __syncthreads();
    if (t < 8) {
        float acc = 0.f;
        #pragma unroll
        for (int wgi = 0; wgi < 8; wgi++) acc += rsm[t * 8 + wgi];
        atomicAdd(&g_acc[t], (double)acc);
        __threadfence();
    }
    __syncthreads();

    // ---- grid barrier (296 blocks, 2/SM, all co-resident) ----
    if (t == 0) {
        unsigned r = atomicAdd(&g_cnt, 1u);
        if (r == gridDim.x - 1u) {
            #pragma unroll
            for (int c2 = 0; c2 < NC; c2++) {
                double m = g_acc[c2] * (double)invB;
                double v = g_acc[4 + c2] * (double)invB - m * m;
                float inv = rsqrtf((float)v + 1e-5f);
                g_scale[c2] = gamma[c2] * inv;
                g_shift[c2] = beta[c2] - (float)m * inv * gamma[c2];
            }
            __threadfence();
            atomicExch(&g_flag, 1);
        } else {
            while (atomicAdd(&g_flag, 0) == 0) __nanosleep(64);
        }
    }
    __syncthreads();

    float sc[4], sh[4];
    #pragma unroll
    for (int c2 = 0; c2 < NC; c2++) {
        sc[c2] = *((volatile float*)&g_scale[c2]);
        sh[c2] = *((volatile float*)&g_shift[c2]);
    }

    // ---- coalesced normalized write from smem-held logits ----
    float4* o4 = (float4*)out;
    #pragma unroll 1
    for (int it = 0; it < MAX_IT; it++) {
        int u = b + it * GRID;
        if (u >= units) break;
        float4 l = *(const float4*)(lsm + (unsigned)(it * 256 + t) * 4u);
        o4[(size_t)u * 256 + t] =
            make_float4(l.x*sc[0]+sh[0], l.y*sc[1]+sh[1], l.z*sc[2]+sh[2], l.w*sc[3]+sh[3]);
    }
}

extern "C" void kernel_launch(void* const* d_in, const int* in_sizes, int n_in,
                              void* d_out, int out_size) {
    const float* x     = (const float*)d_in[0];
    const float* wts   = (const float*)d_in[1];
    const float* W     = (const float*)d_in[2];
    const float* bias  = (const float*)d_in[3];
    const float* gamma = (const float*)d_in[4];
    const float* beta  = (const float*)d_in[5];
    float* out = (float*)d_out;

    int B = in_sizes[0] / 144;          // 262144
    int units = B / 256;                // 1024

    cudaFuncSetAttribute(k_persist, cudaFuncAttributeMaxDynamicSharedMemorySize, SMEM_BYTES);

    k_init<<<1, 32>>>();
    k_persist<<<GRID, BLK, SMEM_BYTES>>>(x, wts, W, bias, gamma, beta, out,
                                         units, 1.0f / (float)B);
}